// round 1
// baseline (speedup 1.0000x reference)
#include <cuda_runtime.h>
#include <math.h>

#define BSZ 32
#define QN  600
#define NC  152
#define TT  32
#define NT  (BSZ*TT)      // 1024 targets
#define NR  (BSZ*QN)      // 19200 rows
#define ROWS 16           // rows per cost block (one warp per row)
#define CTHREADS (ROWS*32)

// ---------------------------------------------------------------------------
// Kernel 1: build cost matrices C[bs*Q, bs*T] for sub (z=0) and obj (z=1).
// One warp per prediction row; targets staged in shared; softmax probs in shared.
// ---------------------------------------------------------------------------
__global__ __launch_bounds__(CTHREADS) void cost_kernel(
    const float* __restrict__ lg0, const float* __restrict__ lg1,
    const float* __restrict__ bx0, const float* __restrict__ bx1,
    const float* __restrict__ tb0, const float* __restrict__ tb1,
    const int*   __restrict__ id0, const int*   __restrict__ id1,
    float* __restrict__ out)
{
    const int which = blockIdx.z;
    const float* __restrict__ logits = which ? lg1 : lg0;
    const float* __restrict__ boxes  = which ? bx1 : bx0;
    const float* __restrict__ tbbox  = which ? tb1 : tb0;
    const int*   __restrict__ tids   = which ? id1 : id0;
    float* __restrict__ C = out + (size_t)which * ((size_t)NR * NT);

    __shared__ float s_cx[NT], s_cy[NT], s_w[NT], s_h[NT];
    __shared__ float s_x0[NT], s_y0[NT], s_x1[NT], s_y1[NT];
    __shared__ int   s_id[NT];
    __shared__ float s_prob[ROWS][NC];

    const int tid = threadIdx.x;

    for (int j = tid; j < NT; j += CTHREADS) {
        float cx = tbbox[j*4+0], cy = tbbox[j*4+1];
        float w  = tbbox[j*4+2], h  = tbbox[j*4+3];
        s_cx[j] = cx; s_cy[j] = cy; s_w[j] = w; s_h[j] = h;
        s_x0[j] = cx - 0.5f*w; s_y0[j] = cy - 0.5f*h;
        s_x1[j] = cx + 0.5f*w; s_y1[j] = cy + 0.5f*h;
        s_id[j] = tids[j];
    }

    const int warp = tid >> 5, lane = tid & 31;
    const int row  = blockIdx.x * ROWS + warp;      // always < NR (1200 blocks)
    const float* lrow = logits + (size_t)row * NC;

    // softmax over NC classes (warp-cooperative), store probs to shared
    float m = -1e30f;
    for (int k = lane; k < NC; k += 32) m = fmaxf(m, lrow[k]);
    #pragma unroll
    for (int o = 16; o; o >>= 1) m = fmaxf(m, __shfl_xor_sync(~0u, m, o));
    float s = 0.f;
    for (int k = lane; k < NC; k += 32) s += expf(lrow[k] - m);
    #pragma unroll
    for (int o = 16; o; o >>= 1) s += __shfl_xor_sync(~0u, s, o);
    for (int k = lane; k < NC; k += 32) s_prob[warp][k] = expf(lrow[k] - m) / s;
    __syncthreads();

    // per-row box prep
    const float ocx = boxes[row*4+0], ocy = boxes[row*4+1];
    const float ow  = boxes[row*4+2], oh  = boxes[row*4+3];
    const float ox0 = ocx - 0.5f*ow, oy0 = ocy - 0.5f*oh;
    const float ox1 = ocx + 0.5f*ow, oy1 = ocy + 0.5f*oh;
    const float oarea = (ox1 - ox0) * (oy1 - oy0);

    float* __restrict__ orow = C + (size_t)row * NT;
    const float* pr = s_prob[warp];

    for (int j = lane; j < NT; j += 32) {
        float l1 = fabsf(ocx - s_cx[j]) + fabsf(ocy - s_cy[j])
                 + fabsf(ow  - s_w[j])  + fabsf(oh  - s_h[j]);
        float tx0 = s_x0[j], ty0 = s_y0[j], tx1 = s_x1[j], ty1 = s_y1[j];
        float ta  = (tx1 - tx0) * (ty1 - ty0);
        float ltx = fmaxf(ox0, tx0), lty = fmaxf(oy0, ty0);
        float rbx = fminf(ox1, tx1), rby = fminf(oy1, ty1);
        float iw  = fmaxf(rbx - ltx, 0.f), ih = fmaxf(rby - lty, 0.f);
        float inter = iw * ih;
        float uni   = oarea + ta - inter;
        float cx0 = fminf(ox0, tx0), cy0 = fminf(oy0, ty0);
        float cx1 = fmaxf(ox1, tx1), cy1 = fmaxf(oy1, ty1);
        float cw  = fmaxf(cx1 - cx0, 0.f), ch = fmaxf(cy1 - cy0, 0.f);
        float ac  = cw * ch;
        float iou  = __fdividef(inter, uni);
        float giou = iou - __fdividef(ac - uni, ac);
        orow[j] = l1 - pr[s_id[j]] - giou;
    }
}

// ---------------------------------------------------------------------------
// Kernel 2: exact rectangular JV assignment per (batch, sub/obj) on the
// diagonal 32x600 block, doubles throughout (mirrors float64 reference).
// One block per problem. 64 blocks total.
// ---------------------------------------------------------------------------
#define MT 256

struct MatchSmem {
    double v[QN+1];
    double minv[QN+1];
    double u[TT+1];
    double wred[MT/32];
    int    ired[MT/32];
    int    p[QN+1];
    int    way[QN+1];
    int    used[QN+1];
    float  cost[TT*QN];       // cost[t*QN + q]
};

__global__ __launch_bounds__(MT) void match_kernel(
    const float* __restrict__ Cfull, float* __restrict__ outbase)
{
    extern __shared__ unsigned char smem_raw[];
    MatchSmem* sm = reinterpret_cast<MatchSmem*>(smem_raw);

    const int b     = blockIdx.x & 31;
    const int which = blockIdx.x >> 5;
    const float* __restrict__ C = Cfull + (size_t)which * ((size_t)NR * NT);
    const int tid = threadIdx.x;
    const int warp = tid >> 5, lane = tid & 31;
    const double INF = 1e18;

    // stage diagonal block: cost[t][q] = C[b, q, b*T + t]
    for (int idx = tid; idx < TT*QN; idx += MT) {
        int q = idx >> 5, t = idx & 31;
        sm->cost[t*QN + q] = C[((size_t)(b*QN + q))*NT + b*TT + t];
    }
    for (int j = tid; j <= QN; j += MT) { sm->v[j] = 0.0; sm->p[j] = 0; }
    if (tid <= TT) sm->u[tid] = 0.0;
    __syncthreads();

    for (int i = 1; i <= TT; i++) {
        if (tid == 0) sm->p[0] = i;
        for (int j = tid; j <= QN; j += MT) { sm->minv[j] = INF; sm->used[j] = 0; }
        __syncthreads();

        int j0 = 0;
        while (true) {
            if (tid == 0) sm->used[j0] = 1;
            __syncthreads();
            const int i0 = sm->p[j0];
            const double ui0 = sm->u[i0];
            const float* crow = sm->cost + (i0 - 1) * QN;

            double lmin = INF; int lidx = 0x7fffffff;
            for (int j = 1 + tid; j <= QN; j += MT) {
                if (!sm->used[j]) {
                    double cur = (double)crow[j-1] - ui0 - sm->v[j];
                    double mv  = sm->minv[j];
                    if (cur < mv) { sm->minv[j] = cur; sm->way[j] = j0; mv = cur; }
                    if (mv < lmin || (mv == lmin && j < lidx)) { lmin = mv; lidx = j; }
                }
            }
            // argmin reduction, first-index tie-break (matches np.argmin)
            #pragma unroll
            for (int o = 16; o; o >>= 1) {
                double om = __shfl_xor_sync(~0u, lmin, o);
                int    oi = __shfl_xor_sync(~0u, lidx, o);
                if (om < lmin || (om == lmin && oi < lidx)) { lmin = om; lidx = oi; }
            }
            if (lane == 0) { sm->wred[warp] = lmin; sm->ired[warp] = lidx; }
            __syncthreads();
            if (tid == 0) {
                double bm = sm->wred[0]; int bi = sm->ired[0];
                #pragma unroll
                for (int w = 1; w < MT/32; w++)
                    if (sm->wred[w] < bm || (sm->wred[w] == bm && sm->ired[w] < bi))
                        { bm = sm->wred[w]; bi = sm->ired[w]; }
                sm->wred[0] = bm; sm->ired[0] = bi;
            }
            __syncthreads();
            const double delta = sm->wred[0];
            const int j1 = sm->ired[0];

            for (int j = tid; j <= QN; j += MT) {
                if (sm->used[j]) { sm->u[sm->p[j]] += delta; sm->v[j] -= delta; }
                else             sm->minv[j] -= delta;
            }
            __syncthreads();
            j0 = j1;
            if (sm->p[j0] == 0) break;
        }
        // augment
        if (tid == 0) {
            int j = j0;
            while (j) { int jn = sm->way[j]; sm->p[j] = sm->p[jn]; j = jn; }
        }
        __syncthreads();
    }

    // emit: cols sorted ascending (natural order), rows = p-1
    if (tid == 0) {
        float* op = outbase + (size_t)2*NR*NT + (size_t)which * 2 * NT;  // ps / po
        float* ot = op + NT;                                             // ts / to
        int k = 0;
        for (int q = 1; q <= QN; q++) {
            if (sm->p[q]) {
                op[b*TT + k] = (float)(q - 1);
                ot[b*TT + k] = (float)(sm->p[q] - 1);
                k++;
            }
        }
    }
}

// ---------------------------------------------------------------------------
extern "C" void kernel_launch(void* const* d_in, const int* in_sizes, int n_in,
                              void* d_out, int out_size) {
    const float* lg0 = (const float*)d_in[0];
    const float* lg1 = (const float*)d_in[1];
    const float* bx0 = (const float*)d_in[2];
    const float* bx1 = (const float*)d_in[3];
    const float* tb0 = (const float*)d_in[4];
    const float* tb1 = (const float*)d_in[5];
    const int*   id0 = (const int*)d_in[6];
    const int*   id1 = (const int*)d_in[7];
    float* out = (float*)d_out;

    cudaFuncSetAttribute(match_kernel,
                         cudaFuncAttributeMaxDynamicSharedMemorySize,
                         (int)sizeof(MatchSmem));

    dim3 cg(NR/ROWS, 1, 2);
    cost_kernel<<<cg, CTHREADS>>>(lg0, lg1, bx0, bx1, tb0, tb1, id0, id1, out);
    match_kernel<<<64, MT, sizeof(MatchSmem)>>>(out, out);
}